// round 1
// baseline (speedup 1.0000x reference)
#include <cuda_runtime.h>
#include <math.h>
#include <stdint.h>

#define N_NODES 20000
#define N_EDGES 320000
#define DIM     256      // = H*F = D_N = D_E
#define NHEAD   4
#define FDIM    64

// ---------------- scratch (static device globals; no allocation) -------------
__device__ float g_ft [(size_t)N_NODES * DIM];        // node projections (N,256)
__device__ float g_ftp[(size_t)N_EDGES * DIM];        // ft[src]+eft      (E,256)
__device__ float g_a  [(size_t)N_EDGES * NHEAD];      // logits / exp     (E,4)
__device__ float g_m  [(size_t)N_NODES * NHEAD];      // segment max      (N,4)
__device__ float g_s  [(size_t)N_NODES * NHEAD];      // segment sum      (N,4)

// ---------------- init: zero output, init m/s --------------------------------
__global__ void init_kernel(float* __restrict__ out) {
    int i = blockIdx.x * blockDim.x + threadIdx.x;
    if (i < N_NODES * DIM) out[i] = 0.0f;
    if (i < N_NODES * NHEAD) { g_m[i] = -INFINITY; g_s[i] = 0.0f; }
}

// ---------------- fp32 GEMM: C[M,256] = A[M,256] @ W[256,256] ----------------
// Block: 256 threads, tile BM=32 rows x BN=256 cols, BK=32.
// Thread: 4 consecutive cols (float4) x 8 rows = 32 accumulators.
// FUSE variant (edge GEMM): epilogue adds ft[src], writes g_ftp, and computes
// per-head dot with ft[dst] (16-lane shfl reduction -> g_a). Non-fused writes g_ft.
template <bool FUSE>
__global__ __launch_bounds__(256) void gemm_kernel(
    const float* __restrict__ A, const float* __restrict__ W,
    const int* __restrict__ src, const int* __restrict__ dst, int M)
{
    __shared__ float As[32][32];
    __shared__ float Bs[32][256];

    const int tid = threadIdx.x;
    const int m0  = blockIdx.x * 32;

    const int cg = tid & 63;          // column group 0..63
    const int c  = cg << 2;           // column 0..252 (float4)
    const int r0 = (tid >> 6) << 3;   // row base 0..24 step 8

    float4 acc[8];
#pragma unroll
    for (int i = 0; i < 8; i++) acc[i] = make_float4(0.f, 0.f, 0.f, 0.f);

    const int arow = tid >> 3;        // A-load: row 0..31
    const int ak   = (tid & 7) << 2;  //         k-col 0..28 step 4

#pragma unroll 1
    for (int kb = 0; kb < DIM; kb += 32) {
        // load A tile: 32x32 (one float4 per thread)
        *(float4*)&As[arow][ak] =
            *(const float4*)&A[(size_t)(m0 + arow) * DIM + kb + ak];
        // load B tile: 32x256 (8 float4 per thread)
#pragma unroll
        for (int j = 0; j < 8; j++) {
            int f4 = tid + j * 256;           // 0..2047
            int bk = f4 >> 6, bc = (f4 & 63) << 2;
            *(float4*)&Bs[bk][bc] =
                *(const float4*)&W[(size_t)(kb + bk) * DIM + bc];
        }
        __syncthreads();

#pragma unroll
        for (int k4 = 0; k4 < 8; k4++) {
            float4 b0 = *(const float4*)&Bs[k4 * 4 + 0][c];
            float4 b1 = *(const float4*)&Bs[k4 * 4 + 1][c];
            float4 b2 = *(const float4*)&Bs[k4 * 4 + 2][c];
            float4 b3 = *(const float4*)&Bs[k4 * 4 + 3][c];
#pragma unroll
            for (int i = 0; i < 8; i++) {
                float4 a = *(const float4*)&As[r0 + i][k4 * 4];
                acc[i].x += a.x * b0.x + a.y * b1.x + a.z * b2.x + a.w * b3.x;
                acc[i].y += a.x * b0.y + a.y * b1.y + a.z * b2.y + a.w * b3.y;
                acc[i].z += a.x * b0.z + a.y * b1.z + a.z * b2.z + a.w * b3.z;
                acc[i].w += a.x * b0.w + a.y * b1.w + a.z * b2.w + a.w * b3.w;
            }
        }
        __syncthreads();
    }

    if (!FUSE) {
#pragma unroll
        for (int i = 0; i < 8; i++)
            *(float4*)&g_ft[(size_t)(m0 + r0 + i) * DIM + c] = acc[i];
    } else {
        const int h = cg >> 4;  // head 0..3 (16 col-groups per head)
#pragma unroll
        for (int i = 0; i < 8; i++) {
            int e  = m0 + r0 + i;
            int sn = src[e], dn = dst[e];
            float4 fs = *(const float4*)&g_ft[(size_t)sn * DIM + c];
            float4 fd = *(const float4*)&g_ft[(size_t)dn * DIM + c];
            float4 fp;
            fp.x = acc[i].x + fs.x;
            fp.y = acc[i].y + fs.y;
            fp.z = acc[i].z + fs.z;
            fp.w = acc[i].w + fs.w;
            *(float4*)&g_ftp[(size_t)e * DIM + c] = fp;
            float pd = fp.x * fd.x + fp.y * fd.y + fp.z * fd.z + fp.w * fd.w;
            // reduce over the 16 lanes covering this (edge, head)
            pd += __shfl_xor_sync(0xffffffffu, pd, 8);
            pd += __shfl_xor_sync(0xffffffffu, pd, 4);
            pd += __shfl_xor_sync(0xffffffffu, pd, 2);
            pd += __shfl_xor_sync(0xffffffffu, pd, 1);
            if ((tid & 15) == 0)
                g_a[(size_t)e * NHEAD + h] = pd;
        }
    }
}

// ---------------- segment max via CAS float-max -------------------------------
__device__ __forceinline__ void atomicMaxF(float* addr, float val) {
    int old = __float_as_int(*addr);
    while (__int_as_float(old) < val) {
        int assumed = old;
        old = atomicCAS((int*)addr, assumed, __float_as_int(val));
        if (old == assumed) break;
    }
}

__global__ void segmax_kernel(const int* __restrict__ dst) {
    int i = blockIdx.x * blockDim.x + threadIdx.x;   // E*H threads
    if (i >= N_EDGES * NHEAD) return;
    int e = i >> 2, h = i & 3;
    atomicMaxF(&g_m[(size_t)dst[e] * NHEAD + h], g_a[i]);
}

// ---------------- exp + segment sum -------------------------------------------
__global__ void expsum_kernel(const int* __restrict__ dst) {
    int i = blockIdx.x * blockDim.x + threadIdx.x;   // E*H threads
    if (i >= N_EDGES * NHEAD) return;
    int e = i >> 2, h = i & 3;
    int d = dst[e];
    float ex = expf(g_a[i] - g_m[(size_t)d * NHEAD + h]);
    g_a[i] = ex;
    atomicAdd(&g_s[(size_t)d * NHEAD + h], ex);
}

// ---------------- weighted scatter-sum aggregation ----------------------------
__global__ void agg_kernel(const int* __restrict__ dst, float* __restrict__ out) {
    int t = blockIdx.x * blockDim.x + threadIdx.x;   // E*64 threads
    if (t >= N_EDGES * 64) return;
    int e  = t >> 6;
    int c  = (t & 63) << 2;     // column 0..252
    int h  = c >> 6;            // head
    int d  = dst[e];
    float sa = g_a[(size_t)e * NHEAD + h] / g_s[(size_t)d * NHEAD + h] * 0.125f;
    float4 fp = *(const float4*)&g_ftp[(size_t)e * DIM + c];
    float* o = &out[(size_t)d * DIM + c];
    atomicAdd(o + 0, sa * fp.x);
    atomicAdd(o + 1, sa * fp.y);
    atomicAdd(o + 2, sa * fp.z);
    atomicAdd(o + 3, sa * fp.w);
}

// ---------------- launch -------------------------------------------------------
extern "C" void kernel_launch(void* const* d_in, const int* in_sizes, int n_in,
                              void* d_out, int out_size) {
    const float* nfeat  = (const float*)d_in[0];
    const float* efeat  = (const float*)d_in[1];
    const int*   src    = (const int*)  d_in[2];
    const int*   dst    = (const int*)  d_in[3];
    const float* W_node = (const float*)d_in[4];
    const float* W_edge = (const float*)d_in[5];
    float* out = (float*)d_out;

    // 1. init: zero output, init segment max/sum
    init_kernel<<<(N_NODES * DIM + 255) / 256, 256>>>(out);

    // 2. node projection: g_ft = nfeat @ W_node   (20000 rows, 625 blocks)
    gemm_kernel<false><<<N_NODES / 32, 256>>>(nfeat, W_node, nullptr, nullptr, N_NODES);

    // 3. fused edge GEMM + gather-add + per-head dot (10000 blocks)
    gemm_kernel<true><<<N_EDGES / 32, 256>>>(efeat, W_edge, src, dst, N_EDGES);

    // 4. segment max over destination nodes
    segmax_kernel<<<(N_EDGES * NHEAD + 255) / 256, 256>>>(dst);

    // 5. exp + segment sum
    expsum_kernel<<<(N_EDGES * NHEAD + 255) / 256, 256>>>(dst);

    // 6. weighted scatter aggregation
    agg_kernel<<<(N_EDGES * 64 + 255) / 256, 256>>>(dst, out);
}

// round 2
// speedup vs baseline: 1.4846x; 1.4846x over previous
#include <cuda_runtime.h>
#include <cuda_bf16.h>
#include <math.h>
#include <stdint.h>

#define N_NODES 20000
#define N_EDGES 320000
#define DIM     256      // = H*F = D_N = D_E
#define NHEAD   4
#define FDIM    64

// ---------------- scratch (static device globals; no allocation) -------------
__device__ float g_ft [(size_t)N_NODES * DIM];        // node projections (N,256)
__device__ float g_ftp[(size_t)N_EDGES * DIM];        // ft[src]+eft      (E,256)
__device__ float g_a  [(size_t)N_EDGES * NHEAD];      // logits / exp     (E,4)
__device__ float g_m  [(size_t)N_NODES * NHEAD];      // segment max      (N,4)
__device__ float g_s  [(size_t)N_NODES * NHEAD];      // segment sum      (N,4)

// ---------------- init: zero output, init m/s --------------------------------
__global__ void init_kernel(float* __restrict__ out) {
    int i = blockIdx.x * blockDim.x + threadIdx.x;
    if (i < N_NODES * DIM) out[i] = 0.0f;
    if (i < N_NODES * NHEAD) { g_m[i] = -INFINITY; g_s[i] = 0.0f; }
}

// ---------------- mma / ldmatrix helpers --------------------------------------
__device__ __forceinline__ void ldsm_x4(uint32_t* r, const void* p) {
    uint32_t a = (uint32_t)__cvta_generic_to_shared(p);
    asm volatile("ldmatrix.sync.aligned.m8n8.x4.shared.b16 {%0,%1,%2,%3}, [%4];"
        : "=r"(r[0]), "=r"(r[1]), "=r"(r[2]), "=r"(r[3]) : "r"(a));
}
__device__ __forceinline__ void ldsm_x4_t(uint32_t* r, const void* p) {
    uint32_t a = (uint32_t)__cvta_generic_to_shared(p);
    asm volatile("ldmatrix.sync.aligned.m8n8.x4.trans.shared.b16 {%0,%1,%2,%3}, [%4];"
        : "=r"(r[0]), "=r"(r[1]), "=r"(r[2]), "=r"(r[3]) : "r"(a));
}
__device__ __forceinline__ void mma_bf16(float* c, const uint32_t* a, const uint32_t* b) {
    asm volatile(
        "mma.sync.aligned.m16n8k16.row.col.f32.bf16.bf16.f32 "
        "{%0,%1,%2,%3}, {%4,%5,%6,%7}, {%8,%9}, {%0,%1,%2,%3};"
        : "+f"(c[0]), "+f"(c[1]), "+f"(c[2]), "+f"(c[3])
        : "r"(a[0]), "r"(a[1]), "r"(a[2]), "r"(a[3]), "r"(b[0]), "r"(b[1]));
}
__device__ __forceinline__ __nv_bfloat162 split_hi(float x, float y) {
    return __nv_bfloat162(__float2bfloat16_rn(x), __float2bfloat16_rn(y));
}
__device__ __forceinline__ __nv_bfloat162 split_lo(float x, float y, __nv_bfloat162 h) {
    return __nv_bfloat162(__float2bfloat16_rn(x - __bfloat162float(h.x)),
                          __float2bfloat16_rn(y - __bfloat162float(h.y)));
}

// ---------------- bf16x2 tensor-core GEMM: C[M,256] = A[M,256] @ W[256,256] ----
// Block: 256 threads (8 warps: 2 in m x 4 in n). Tile BM=32, BN=256, BK=32.
// Warp tile 16x64 (one head per warp). fp32 operands split into hi/lo bf16;
// 3 mma terms per fragment (hi*hi + hi*lo + lo*hi) recover ~fp32 precision.
// FUSE: epilogue adds ft[src], writes g_ftp, per-head dot with ft[dst] -> g_a.
template <bool FUSE>
__global__ __launch_bounds__(256) void gemm_mma_kernel(
    const float* __restrict__ A, const float* __restrict__ W,
    const int* __restrict__ src, const int* __restrict__ dst)
{
    __shared__ __nv_bfloat16 As_hi[32][40],  As_lo[32][40];    // pad 8: LDSM conflict-free
    __shared__ __nv_bfloat16 Bs_hi[32][264], Bs_lo[32][264];   // pad 8

    const int tid  = threadIdx.x;
    const int lane = tid & 31;
    const int warp = tid >> 5;
    const int wm   = warp & 1;          // warp m index (0..1)
    const int wn   = warp >> 1;         // warp n index (0..3) == head
    const int m0   = blockIdx.x * 32;

    const int lrow  = lane & 15;        // ldmatrix row-provider index
    const int lcol8 = (lane >> 4) * 8;  // ldmatrix k/n half select

    float acc[8][4];
#pragma unroll
    for (int i = 0; i < 8; i++)
#pragma unroll
        for (int j = 0; j < 4; j++) acc[i][j] = 0.0f;

#pragma unroll 1
    for (int kb = 0; kb < DIM; kb += 32) {
        // stage A tile (32x32): one float4 per thread, split hi/lo
        {
            int r = tid >> 3, kc = (tid & 7) << 2;
            float4 v = *(const float4*)&A[(size_t)(m0 + r) * DIM + kb + kc];
            __nv_bfloat162 h0 = split_hi(v.x, v.y), h1 = split_hi(v.z, v.w);
            *(__nv_bfloat162*)&As_hi[r][kc]     = h0;
            *(__nv_bfloat162*)&As_hi[r][kc + 2] = h1;
            *(__nv_bfloat162*)&As_lo[r][kc]     = split_lo(v.x, v.y, h0);
            *(__nv_bfloat162*)&As_lo[r][kc + 2] = split_lo(v.z, v.w, h1);
        }
        // stage B tile (32x256): 8 float4 per thread
#pragma unroll
        for (int j = 0; j < 8; j++) {
            int f4 = tid + j * 256;
            int k = f4 >> 6, n0 = (f4 & 63) << 2;
            float4 v = *(const float4*)&W[(size_t)(kb + k) * DIM + n0];
            __nv_bfloat162 h0 = split_hi(v.x, v.y), h1 = split_hi(v.z, v.w);
            *(__nv_bfloat162*)&Bs_hi[k][n0]     = h0;
            *(__nv_bfloat162*)&Bs_hi[k][n0 + 2] = h1;
            *(__nv_bfloat162*)&Bs_lo[k][n0]     = split_lo(v.x, v.y, h0);
            *(__nv_bfloat162*)&Bs_lo[k][n0 + 2] = split_lo(v.z, v.w, h1);
        }
        __syncthreads();

#pragma unroll
        for (int ks = 0; ks < 2; ks++) {
            const int kofs = ks * 16;
            uint32_t ah[4], al[4];
            ldsm_x4(ah, &As_hi[wm * 16 + lrow][kofs + lcol8]);
            ldsm_x4(al, &As_lo[wm * 16 + lrow][kofs + lcol8]);
#pragma unroll
            for (int p = 0; p < 4; p++) {           // pair of n-fragments
                const int nb = wn * 64 + p * 16;
                uint32_t bh[4], bl[4];
                ldsm_x4_t(bh, &Bs_hi[kofs + lrow][nb + lcol8]);
                ldsm_x4_t(bl, &Bs_lo[kofs + lrow][nb + lcol8]);
                mma_bf16(acc[2 * p],     ah, bh);
                mma_bf16(acc[2 * p],     ah, bl);
                mma_bf16(acc[2 * p],     al, bh);
                mma_bf16(acc[2 * p + 1], ah, bh + 2);
                mma_bf16(acc[2 * p + 1], ah, bl + 2);
                mma_bf16(acc[2 * p + 1], al, bh + 2);
            }
        }
        __syncthreads();
    }

    // epilogue: C fragment owner map — c0,c1: (row g, col 2*tig,+1); c2,c3: row g+8
    const int g   = lane >> 2;
    const int tig = lane & 3;
    const int row0 = m0 + wm * 16 + g;

    if (!FUSE) {
#pragma unroll
        for (int half = 0; half < 2; half++) {
            int r = row0 + half * 8;
#pragma unroll
            for (int nf = 0; nf < 8; nf++) {
                int col = wn * 64 + nf * 8 + tig * 2;
                *(float2*)&g_ft[(size_t)r * DIM + col] =
                    make_float2(acc[nf][half * 2], acc[nf][half * 2 + 1]);
            }
        }
    } else {
#pragma unroll
        for (int half = 0; half < 2; half++) {
            int e  = row0 + half * 8;
            int sn = src[e], dn = dst[e];
            float dot = 0.0f;
#pragma unroll
            for (int nf = 0; nf < 8; nf++) {
                int col = wn * 64 + nf * 8 + tig * 2;
                float2 fs = *(const float2*)&g_ft[(size_t)sn * DIM + col];
                float2 fd = *(const float2*)&g_ft[(size_t)dn * DIM + col];
                float px = acc[nf][half * 2]     + fs.x;
                float py = acc[nf][half * 2 + 1] + fs.y;
                *(float2*)&g_ftp[(size_t)e * DIM + col] = make_float2(px, py);
                dot += px * fd.x + py * fd.y;
            }
            // reduce over the 4 tig-lanes covering this (edge, head)
            dot += __shfl_xor_sync(0xffffffffu, dot, 1);
            dot += __shfl_xor_sync(0xffffffffu, dot, 2);
            if (tig == 0)
                g_a[(size_t)e * NHEAD + wn] = dot;
        }
    }
}

// ---------------- segment max via CAS float-max -------------------------------
__device__ __forceinline__ void atomicMaxF(float* addr, float val) {
    int old = __float_as_int(*addr);
    while (__int_as_float(old) < val) {
        int assumed = old;
        old = atomicCAS((int*)addr, assumed, __float_as_int(val));
        if (old == assumed) break;
    }
}

__global__ void segmax_kernel(const int* __restrict__ dst) {
    int i = blockIdx.x * blockDim.x + threadIdx.x;   // E*H threads
    if (i >= N_EDGES * NHEAD) return;
    int e = i >> 2, h = i & 3;
    atomicMaxF(&g_m[(size_t)dst[e] * NHEAD + h], g_a[i]);
}

// ---------------- exp + segment sum -------------------------------------------
__global__ void expsum_kernel(const int* __restrict__ dst) {
    int i = blockIdx.x * blockDim.x + threadIdx.x;   // E*H threads
    if (i >= N_EDGES * NHEAD) return;
    int e = i >> 2, h = i & 3;
    int d = dst[e];
    float ex = expf(g_a[i] - g_m[(size_t)d * NHEAD + h]);
    g_a[i] = ex;
    atomicAdd(&g_s[(size_t)d * NHEAD + h], ex);
}

// ---------------- weighted scatter-sum aggregation ----------------------------
__global__ void agg_kernel(const int* __restrict__ dst, float* __restrict__ out) {
    int t = blockIdx.x * blockDim.x + threadIdx.x;   // E*64 threads
    if (t >= N_EDGES * 64) return;
    int e  = t >> 6;
    int c  = (t & 63) << 2;     // column 0..252
    int h  = c >> 6;            // head
    int d  = dst[e];
    float sa = g_a[(size_t)e * NHEAD + h] / g_s[(size_t)d * NHEAD + h] * 0.125f;
    float4 fp = *(const float4*)&g_ftp[(size_t)e * DIM + c];
    float* o = &out[(size_t)d * DIM + c];
    atomicAdd(o + 0, sa * fp.x);
    atomicAdd(o + 1, sa * fp.y);
    atomicAdd(o + 2, sa * fp.z);
    atomicAdd(o + 3, sa * fp.w);
}

// ---------------- launch -------------------------------------------------------
extern "C" void kernel_launch(void* const* d_in, const int* in_sizes, int n_in,
                              void* d_out, int out_size) {
    const float* nfeat  = (const float*)d_in[0];
    const float* efeat  = (const float*)d_in[1];
    const int*   src    = (const int*)  d_in[2];
    const int*   dst    = (const int*)  d_in[3];
    const float* W_node = (const float*)d_in[4];
    const float* W_edge = (const float*)d_in[5];
    float* out = (float*)d_out;

    // 1. init: zero output, init segment max/sum
    init_kernel<<<(N_NODES * DIM + 255) / 256, 256>>>(out);

    // 2. node projection: g_ft = nfeat @ W_node  (625 blocks)
    gemm_mma_kernel<false><<<N_NODES / 32, 256>>>(nfeat, W_node, nullptr, nullptr);

    // 3. fused edge GEMM + gather-add + per-head dot (10000 blocks)
    gemm_mma_kernel<true><<<N_EDGES / 32, 256>>>(efeat, W_edge, src, dst);

    // 4. segment max over destination nodes
    segmax_kernel<<<(N_EDGES * NHEAD + 255) / 256, 256>>>(dst);

    // 5. exp + segment sum
    expsum_kernel<<<(N_EDGES * NHEAD + 255) / 256, 256>>>(dst);

    // 6. weighted scatter aggregation
    agg_kernel<<<(N_EDGES * 64 + 255) / 256, 256>>>(dst, out);
}

// round 3
// speedup vs baseline: 2.1544x; 1.4512x over previous
#include <cuda_runtime.h>
#include <cuda_bf16.h>
#include <math.h>
#include <stdint.h>

#define N_NODES 20000
#define N_EDGES 320000
#define DIM     256      // = H*F = D_N = D_E
#define NHEAD   4
#define FDIM    64

// ---------------- scratch (static device globals; no allocation) -------------
__device__ float g_ft [(size_t)N_NODES * DIM];        // node projections (N,256)
__device__ float g_ftp[(size_t)N_EDGES * DIM];        // ft[src]+eft      (E,256)
__device__ float g_a  [(size_t)N_EDGES * NHEAD];      // logits / exp     (E,4)
__device__ float g_m  [(size_t)N_NODES * NHEAD];      // segment max      (N,4)
__device__ float g_s  [(size_t)N_NODES * NHEAD];      // segment sum      (N,4)
__device__ __nv_bfloat16 gW_hi[2][DIM * DIM];         // pre-split weights
__device__ __nv_bfloat16 gW_lo[2][DIM * DIM];

// ---------------- init: zero output, init m/s, split weights ------------------
__global__ void init_kernel(float* __restrict__ out,
                            const float* __restrict__ Wn,
                            const float* __restrict__ We) {
    int i = blockIdx.x * blockDim.x + threadIdx.x;
    if (i < N_NODES * DIM) out[i] = 0.0f;
    if (i < N_NODES * NHEAD) { g_m[i] = -INFINITY; g_s[i] = 0.0f; }
    if (i < DIM * DIM) {
        float v = Wn[i];
        __nv_bfloat16 h = __float2bfloat16_rn(v);
        gW_hi[0][i] = h;
        gW_lo[0][i] = __float2bfloat16_rn(v - __bfloat162float(h));
        v = We[i];
        h = __float2bfloat16_rn(v);
        gW_hi[1][i] = h;
        gW_lo[1][i] = __float2bfloat16_rn(v - __bfloat162float(h));
    }
}

// ---------------- mma / ldmatrix helpers --------------------------------------
__device__ __forceinline__ void ldsm_x4(uint32_t* r, const void* p) {
    uint32_t a = (uint32_t)__cvta_generic_to_shared(p);
    asm volatile("ldmatrix.sync.aligned.m8n8.x4.shared.b16 {%0,%1,%2,%3}, [%4];"
        : "=r"(r[0]), "=r"(r[1]), "=r"(r[2]), "=r"(r[3]) : "r"(a));
}
__device__ __forceinline__ void ldsm_x4_t(uint32_t* r, const void* p) {
    uint32_t a = (uint32_t)__cvta_generic_to_shared(p);
    asm volatile("ldmatrix.sync.aligned.m8n8.x4.trans.shared.b16 {%0,%1,%2,%3}, [%4];"
        : "=r"(r[0]), "=r"(r[1]), "=r"(r[2]), "=r"(r[3]) : "r"(a));
}
__device__ __forceinline__ void mma_bf16(float* c, const uint32_t* a, const uint32_t* b) {
    asm volatile(
        "mma.sync.aligned.m16n8k16.row.col.f32.bf16.bf16.f32 "
        "{%0,%1,%2,%3}, {%4,%5,%6,%7}, {%8,%9}, {%0,%1,%2,%3};"
        : "+f"(c[0]), "+f"(c[1]), "+f"(c[2]), "+f"(c[3])
        : "r"(a[0]), "r"(a[1]), "r"(a[2]), "r"(a[3]), "r"(b[0]), "r"(b[1]));
}
__device__ __forceinline__ __nv_bfloat162 split_hi(float x, float y) {
    return __nv_bfloat162(__float2bfloat16_rn(x), __float2bfloat16_rn(y));
}
__device__ __forceinline__ __nv_bfloat162 split_lo(float x, float y, __nv_bfloat162 h) {
    return __nv_bfloat162(__float2bfloat16_rn(x - __bfloat162float(h.x)),
                          __float2bfloat16_rn(y - __bfloat162float(h.y)));
}

// ---------------- bf16x2 tensor-core GEMM: C[M,256] = A[M,256] @ W[256,256] ----
// Block: 256 threads (8 warps: 2 in m x 4 in n). Tile BM=64, BN=256, BK=32.
// Warp tile 32x64 (one head per warp, 2 m-frags). B comes pre-split in bf16.
// FUSE: epilogue adds ft[src], writes g_ftp, per-head dot with ft[dst] -> g_a.
template <bool FUSE>
__global__ __launch_bounds__(256) void gemm_mma_kernel(
    const float* __restrict__ A, int widx,
    const int* __restrict__ src, const int* __restrict__ dst, int M)
{
    __shared__ __nv_bfloat16 As_hi[64][40],  As_lo[64][40];    // pad 8: LDSM conflict-free
    __shared__ __nv_bfloat16 Bs_hi[32][264], Bs_lo[32][264];   // pad 8

    const __nv_bfloat16* __restrict__ Whi = gW_hi[widx];
    const __nv_bfloat16* __restrict__ Wlo = gW_lo[widx];

    const int tid  = threadIdx.x;
    const int lane = tid & 31;
    const int warp = tid >> 5;
    const int wm   = warp & 1;          // warp m index (0..1) -> 32-row slab
    const int wn   = warp >> 1;         // warp n index (0..3) == head
    const int m0   = blockIdx.x * 64;

    const int lrow  = lane & 15;        // ldmatrix row-provider index
    const int lcol8 = (lane >> 4) * 8;  // ldmatrix k/n half select

    float acc[2][8][4];
#pragma unroll
    for (int mf = 0; mf < 2; mf++)
#pragma unroll
        for (int i = 0; i < 8; i++)
#pragma unroll
            for (int j = 0; j < 4; j++) acc[mf][i][j] = 0.0f;

    // A staging coords: 2 float4 per thread per kb (rows 0..31 and 32..63)
    const int ar = tid >> 3;            // 0..31
    const int ak = (tid & 7) << 2;      // 0..28

#pragma unroll 1
    for (int kb = 0; kb < DIM; kb += 32) {
        // stage A tile (64x32 fp32 -> hi/lo bf16)
#pragma unroll
        for (int s = 0; s < 2; s++) {
            int r  = ar + s * 32;
            int mr = m0 + r; if (mr >= M) mr = M - 1;      // tail-safe (node GEMM)
            float4 v = *(const float4*)&A[(size_t)mr * DIM + kb + ak];
            __nv_bfloat162 h0 = split_hi(v.x, v.y), h1 = split_hi(v.z, v.w);
            *(__nv_bfloat162*)&As_hi[r][ak]     = h0;
            *(__nv_bfloat162*)&As_hi[r][ak + 2] = h1;
            *(__nv_bfloat162*)&As_lo[r][ak]     = split_lo(v.x, v.y, h0);
            *(__nv_bfloat162*)&As_lo[r][ak + 2] = split_lo(v.z, v.w, h1);
        }
        // stage B tile (32x256 bf16 hi + lo): pure copy, 4 x uint4 each
#pragma unroll
        for (int j = 0; j < 4; j++) {
            int v8 = tid + j * 256;             // 0..1023 (8-elem vectors)
            int k = v8 >> 5, n0 = (v8 & 31) << 3;
            size_t go = (size_t)(kb + k) * DIM + n0;
            *(uint4*)&Bs_hi[k][n0] = *(const uint4*)&Whi[go];
            *(uint4*)&Bs_lo[k][n0] = *(const uint4*)&Wlo[go];
        }
        __syncthreads();

#pragma unroll
        for (int ks = 0; ks < 2; ks++) {
            const int kofs = ks * 16;
            uint32_t ah[2][4], al[2][4];
#pragma unroll
            for (int mf = 0; mf < 2; mf++) {
                ldsm_x4(ah[mf], &As_hi[wm * 32 + mf * 16 + lrow][kofs + lcol8]);
                ldsm_x4(al[mf], &As_lo[wm * 32 + mf * 16 + lrow][kofs + lcol8]);
            }
#pragma unroll
            for (int p = 0; p < 4; p++) {       // pair of n-fragments
                const int nb = wn * 64 + p * 16;
                uint32_t bh[4], bl[4];
                ldsm_x4_t(bh, &Bs_hi[kofs + lrow][nb + lcol8]);
                ldsm_x4_t(bl, &Bs_lo[kofs + lrow][nb + lcol8]);
#pragma unroll
                for (int mf = 0; mf < 2; mf++) {
                    mma_bf16(acc[mf][2 * p],     ah[mf], bh);
                    mma_bf16(acc[mf][2 * p],     ah[mf], bl);
                    mma_bf16(acc[mf][2 * p],     al[mf], bh);
                    mma_bf16(acc[mf][2 * p + 1], ah[mf], bh + 2);
                    mma_bf16(acc[mf][2 * p + 1], ah[mf], bl + 2);
                    mma_bf16(acc[mf][2 * p + 1], al[mf], bh + 2);
                }
            }
        }
        __syncthreads();
    }

    // epilogue: C fragment owner map — c0,c1: (row g, col 2*tig,+1); c2,c3: row g+8
    const int g   = lane >> 2;
    const int tig = lane & 3;

    if (!FUSE) {
#pragma unroll
        for (int mf = 0; mf < 2; mf++)
#pragma unroll
        for (int half = 0; half < 2; half++) {
            int r = m0 + wm * 32 + mf * 16 + g + half * 8;
            if (r >= M) continue;
#pragma unroll
            for (int nf = 0; nf < 8; nf++) {
                int col = wn * 64 + nf * 8 + tig * 2;
                *(float2*)&g_ft[(size_t)r * DIM + col] =
                    make_float2(acc[mf][nf][half * 2], acc[mf][nf][half * 2 + 1]);
            }
        }
    } else {
#pragma unroll
        for (int mf = 0; mf < 2; mf++)
#pragma unroll
        for (int half = 0; half < 2; half++) {
            int e  = m0 + wm * 32 + mf * 16 + g + half * 8;
            int sn = src[e], dn = dst[e];
            float dot = 0.0f;
#pragma unroll
            for (int nf = 0; nf < 8; nf++) {
                int col = wn * 64 + nf * 8 + tig * 2;
                float2 fs = *(const float2*)&g_ft[(size_t)sn * DIM + col];
                float2 fd = *(const float2*)&g_ft[(size_t)dn * DIM + col];
                float px = acc[mf][nf][half * 2]     + fs.x;
                float py = acc[mf][nf][half * 2 + 1] + fs.y;
                *(float2*)&g_ftp[(size_t)e * DIM + col] = make_float2(px, py);
                dot += px * fd.x + py * fd.y;
            }
            // reduce over the 4 tig-lanes covering this (edge, head)
            dot += __shfl_xor_sync(0xffffffffu, dot, 1);
            dot += __shfl_xor_sync(0xffffffffu, dot, 2);
            if (tig == 0)
                g_a[(size_t)e * NHEAD + wn] = dot;
        }
    }
}

// ---------------- segment max via CAS float-max -------------------------------
__device__ __forceinline__ void atomicMaxF(float* addr, float val) {
    int old = __float_as_int(*addr);
    while (__int_as_float(old) < val) {
        int assumed = old;
        old = atomicCAS((int*)addr, assumed, __float_as_int(val));
        if (old == assumed) break;
    }
}

__global__ void segmax_kernel(const int* __restrict__ dst) {
    int i = blockIdx.x * blockDim.x + threadIdx.x;   // E*H threads
    if (i >= N_EDGES * NHEAD) return;
    int e = i >> 2, h = i & 3;
    atomicMaxF(&g_m[(size_t)dst[e] * NHEAD + h], g_a[i]);
}

// ---------------- exp + segment sum -------------------------------------------
__global__ void expsum_kernel(const int* __restrict__ dst) {
    int i = blockIdx.x * blockDim.x + threadIdx.x;   // E*H threads
    if (i >= N_EDGES * NHEAD) return;
    int e = i >> 2, h = i & 3;
    int d = dst[e];
    float ex = expf(g_a[i] - g_m[(size_t)d * NHEAD + h]);
    g_a[i] = ex;
    atomicAdd(&g_s[(size_t)d * NHEAD + h], ex);
}

// ---------------- weighted scatter-sum aggregation (vector red) ---------------
__global__ void agg_kernel(const int* __restrict__ dst, float* __restrict__ out) {
    int t = blockIdx.x * blockDim.x + threadIdx.x;   // E*64 threads
    if (t >= N_EDGES * 64) return;
    int e  = t >> 6;
    int c  = (t & 63) << 2;     // column 0..252
    int h  = c >> 6;            // head
    int d  = dst[e];
    float sa = g_a[(size_t)e * NHEAD + h] / g_s[(size_t)d * NHEAD + h] * 0.125f;
    float4 fp = *(const float4*)&g_ftp[(size_t)e * DIM + c];
    float* o = &out[(size_t)d * DIM + c];
    asm volatile("red.global.add.v4.f32 [%0], {%1,%2,%3,%4};"
        :: "l"(o), "f"(sa * fp.x), "f"(sa * fp.y), "f"(sa * fp.z), "f"(sa * fp.w)
        : "memory");
}

// ---------------- launch -------------------------------------------------------
extern "C" void kernel_launch(void* const* d_in, const int* in_sizes, int n_in,
                              void* d_out, int out_size) {
    const float* nfeat  = (const float*)d_in[0];
    const float* efeat  = (const float*)d_in[1];
    const int*   src    = (const int*)  d_in[2];
    const int*   dst    = (const int*)  d_in[3];
    const float* W_node = (const float*)d_in[4];
    const float* W_edge = (const float*)d_in[5];
    float* out = (float*)d_out;

    // 1. init: zero output, init segment max/sum, split weights to bf16 hi/lo
    init_kernel<<<(N_NODES * DIM + 255) / 256, 256>>>(out, W_node, W_edge);

    // 2. node projection: g_ft = nfeat @ W_node  (313 blocks, tail-guarded)
    gemm_mma_kernel<false><<<(N_NODES + 63) / 64, 256>>>(nfeat, 0, nullptr, nullptr, N_NODES);

    // 3. fused edge GEMM + gather-add + per-head dot (5000 blocks)
    gemm_mma_kernel<true><<<N_EDGES / 64, 256>>>(efeat, 1, src, dst, N_EDGES);

    // 4. segment max over destination nodes
    segmax_kernel<<<(N_EDGES * NHEAD + 255) / 256, 256>>>(dst);

    // 5. exp + segment sum
    expsum_kernel<<<(N_EDGES * NHEAD + 255) / 256, 256>>>(dst);

    // 6. weighted scatter aggregation
    agg_kernel<<<(N_EDGES * 64 + 255) / 256, 256>>>(dst, out);
}

// round 4
// speedup vs baseline: 2.2394x; 1.0394x over previous
#include <cuda_runtime.h>
#include <cuda_bf16.h>
#include <math.h>
#include <stdint.h>

#define N_NODES 20000
#define N_EDGES 320000
#define DIM     256      // = H*F = D_N = D_E
#define NHEAD   4

#define BM 128
#define BK 32
#define A_LD 40          // padded A row (elems): 80B, multiple of 16B
#define B_LD 264         // padded B row (elems): 528B, multiple of 16B
#define ASZ (BM * A_LD)          // 5120 elems
#define BSZ (BK * B_LD)          // 8448 elems
#define BUFSZ (2 * (ASZ + BSZ))  // 27136 elems per buffer (hi+lo A, hi+lo B)
#define SMEM_BYTES (2 * BUFSZ * 2)  // 108544 bytes

// ---------------- scratch (static device globals; no allocation) -------------
__device__ float    g_ft [(size_t)N_NODES * DIM];     // node projections (N,256)
__device__ float    g_ftp[(size_t)N_EDGES * DIM];     // ft[src]+eft      (E,256)
__device__ float    g_a  [(size_t)N_EDGES * NHEAD];   // logits / exp     (E,4)
__device__ unsigned g_me [(size_t)N_NODES * NHEAD];   // encoded segment max
__device__ float    g_s  [(size_t)N_NODES * NHEAD];   // segment sum      (N,4)
__device__ __nv_bfloat16 gW_hi[2][DIM * DIM];         // pre-split weights
__device__ __nv_bfloat16 gW_lo[2][DIM * DIM];

// ---------------- init: zero output, init m/s, split weights ------------------
__global__ void init_kernel(float* __restrict__ out,
                            const float* __restrict__ Wn,
                            const float* __restrict__ We) {
    int i = blockIdx.x * blockDim.x + threadIdx.x;
    if (i < N_NODES * DIM) out[i] = 0.0f;
    if (i < N_NODES * NHEAD) { g_me[i] = 0u; g_s[i] = 0.0f; }
    if (i < DIM * DIM) {
        float v = Wn[i];
        __nv_bfloat16 h = __float2bfloat16_rn(v);
        gW_hi[0][i] = h;
        gW_lo[0][i] = __float2bfloat16_rn(v - __bfloat162float(h));
        v = We[i];
        h = __float2bfloat16_rn(v);
        gW_hi[1][i] = h;
        gW_lo[1][i] = __float2bfloat16_rn(v - __bfloat162float(h));
    }
}

// ---------------- mma / ldmatrix / cp.async helpers ---------------------------
__device__ __forceinline__ void ldsm_x4(uint32_t* r, const void* p) {
    uint32_t a = (uint32_t)__cvta_generic_to_shared(p);
    asm volatile("ldmatrix.sync.aligned.m8n8.x4.shared.b16 {%0,%1,%2,%3}, [%4];"
        : "=r"(r[0]), "=r"(r[1]), "=r"(r[2]), "=r"(r[3]) : "r"(a));
}
__device__ __forceinline__ void ldsm_x4_t(uint32_t* r, const void* p) {
    uint32_t a = (uint32_t)__cvta_generic_to_shared(p);
    asm volatile("ldmatrix.sync.aligned.m8n8.x4.trans.shared.b16 {%0,%1,%2,%3}, [%4];"
        : "=r"(r[0]), "=r"(r[1]), "=r"(r[2]), "=r"(r[3]) : "r"(a));
}
__device__ __forceinline__ void mma_bf16(float* c, const uint32_t* a, const uint32_t* b) {
    asm volatile(
        "mma.sync.aligned.m16n8k16.row.col.f32.bf16.bf16.f32 "
        "{%0,%1,%2,%3}, {%4,%5,%6,%7}, {%8,%9}, {%0,%1,%2,%3};"
        : "+f"(c[0]), "+f"(c[1]), "+f"(c[2]), "+f"(c[3])
        : "r"(a[0]), "r"(a[1]), "r"(a[2]), "r"(a[3]), "r"(b[0]), "r"(b[1]));
}
__device__ __forceinline__ void cp16(void* sdst, const void* gsrc) {
    uint32_t s = (uint32_t)__cvta_generic_to_shared(sdst);
    asm volatile("cp.async.ca.shared.global [%0], [%1], 16;" :: "r"(s), "l"(gsrc));
}
__device__ __forceinline__ __nv_bfloat162 split_hi(float x, float y) {
    return __nv_bfloat162(__float2bfloat16_rn(x), __float2bfloat16_rn(y));
}
__device__ __forceinline__ __nv_bfloat162 split_lo(float x, float y, __nv_bfloat162 h) {
    return __nv_bfloat162(__float2bfloat16_rn(x - __bfloat162float(h.x)),
                          __float2bfloat16_rn(y - __bfloat162float(h.y)));
}

// ---------------- bf16x2 tensor-core GEMM: C[M,256] = A[M,256] @ W[256,256] ----
// 512 threads (16 warps: 4m x 4n). Tile BM=128, BN=256, BK=32, double-buffered
// smem with cp.async for B (pre-split bf16) and register-prefetched A.
// FUSE: epilogue adds ft[src], writes g_ftp, per-head dot with ft[dst] -> g_a.
template <bool FUSE>
__global__ __launch_bounds__(512) void gemm_mma_kernel(
    const float* __restrict__ A, int widx,
    const int* __restrict__ src, const int* __restrict__ dst, int M)
{
    extern __shared__ __nv_bfloat16 sm[];
    const __nv_bfloat16* __restrict__ Whi = gW_hi[widx];
    const __nv_bfloat16* __restrict__ Wlo = gW_lo[widx];

    const int tid  = threadIdx.x;
    const int lane = tid & 31;
    const int warp = tid >> 5;
    const int wm   = warp & 3;          // warp m index (0..3) -> 32-row slab
    const int wn   = warp >> 2;         // warp n index (0..3) == head
    const int m0   = blockIdx.x * BM;

    const int lrow  = lane & 15;
    const int lcol8 = (lane >> 4) * 8;

    float acc[2][8][4];
#pragma unroll
    for (int mf = 0; mf < 2; mf++)
#pragma unroll
        for (int i = 0; i < 8; i++)
#pragma unroll
            for (int j = 0; j < 4; j++) acc[mf][i][j] = 0.0f;

    // A prefetch coords: 2 float4 per thread (1024 float4 / 512 thr)
    const int af0 = tid, af1 = tid + 512;
    const int ar0 = af0 >> 3, ac0 = (af0 & 7) << 2;
    const int ar1 = af1 >> 3, ac1 = (af1 & 7) << 2;
    int mr0 = m0 + ar0; if (mr0 >= M) mr0 = M - 1;
    int mr1 = m0 + ar1; if (mr1 >= M) mr1 = M - 1;
    float4 areg0, areg1;

#define LOAD_A(kb) do { \
        areg0 = *(const float4*)&A[(size_t)mr0 * DIM + (kb) + ac0]; \
        areg1 = *(const float4*)&A[(size_t)mr1 * DIM + (kb) + ac1]; } while (0)

#define STORE_A(buf) do { \
        __nv_bfloat16* ah_ = sm + (buf) * BUFSZ; \
        __nv_bfloat16* al_ = ah_ + ASZ; \
        __nv_bfloat162 h0 = split_hi(areg0.x, areg0.y), h1 = split_hi(areg0.z, areg0.w); \
        *(__nv_bfloat162*)&ah_[ar0 * A_LD + ac0]     = h0; \
        *(__nv_bfloat162*)&ah_[ar0 * A_LD + ac0 + 2] = h1; \
        *(__nv_bfloat162*)&al_[ar0 * A_LD + ac0]     = split_lo(areg0.x, areg0.y, h0); \
        *(__nv_bfloat162*)&al_[ar0 * A_LD + ac0 + 2] = split_lo(areg0.z, areg0.w, h1); \
        h0 = split_hi(areg1.x, areg1.y); h1 = split_hi(areg1.z, areg1.w); \
        *(__nv_bfloat162*)&ah_[ar1 * A_LD + ac1]     = h0; \
        *(__nv_bfloat162*)&ah_[ar1 * A_LD + ac1 + 2] = h1; \
        *(__nv_bfloat162*)&al_[ar1 * A_LD + ac1]     = split_lo(areg1.x, areg1.y, h0); \
        *(__nv_bfloat162*)&al_[ar1 * A_LD + ac1 + 2] = split_lo(areg1.z, areg1.w, h1); } while (0)

#define CP_B(kb, buf) do { \
        __nv_bfloat16* bh_ = sm + (buf) * BUFSZ + 2 * ASZ; \
        _Pragma("unroll") \
        for (int j = 0; j < 4; j++) { \
            int v = tid + j * 512; \
            int hl = v >> 10; \
            int idx = v & 1023; \
            int k = idx >> 5, n0 = (idx & 31) << 3; \
            const __nv_bfloat16* gsrc = (hl ? Wlo : Whi) + (size_t)((kb) + k) * DIM + n0; \
            cp16(bh_ + hl * BSZ + k * B_LD + n0, gsrc); \
        } \
        asm volatile("cp.async.commit_group;"); } while (0)

    // prologue: fill buffer 0
    LOAD_A(0);
    CP_B(0, 0);
    STORE_A(0);
    asm volatile("cp.async.wait_group 0;");
    __syncthreads();

#pragma unroll 1
    for (int it = 0; it < 8; it++) {
        const int buf = it & 1;
        if (it < 7) {
            CP_B((it + 1) * BK, buf ^ 1);
            LOAD_A((it + 1) * BK);
        }

        const __nv_bfloat16* As_hi = sm + buf * BUFSZ;
        const __nv_bfloat16* As_lo = As_hi + ASZ;
        const __nv_bfloat16* Bs_hi = As_hi + 2 * ASZ;
        const __nv_bfloat16* Bs_lo = Bs_hi + BSZ;

#pragma unroll
        for (int ks = 0; ks < 2; ks++) {
            const int kofs = ks * 16;
            uint32_t ah[2][4], al[2][4];
#pragma unroll
            for (int mf = 0; mf < 2; mf++) {
                ldsm_x4(ah[mf], &As_hi[(wm * 32 + mf * 16 + lrow) * A_LD + kofs + lcol8]);
                ldsm_x4(al[mf], &As_lo[(wm * 32 + mf * 16 + lrow) * A_LD + kofs + lcol8]);
            }
#pragma unroll
            for (int p = 0; p < 4; p++) {
                const int nb = wn * 64 + p * 16;
                uint32_t bh[4], bl[4];
                ldsm_x4_t(bh, &Bs_hi[(kofs + lrow) * B_LD + nb + lcol8]);
                ldsm_x4_t(bl, &Bs_lo[(kofs + lrow) * B_LD + nb + lcol8]);
#pragma unroll
                for (int mf = 0; mf < 2; mf++) {
                    mma_bf16(acc[mf][2 * p],     ah[mf], bh);
                    mma_bf16(acc[mf][2 * p],     ah[mf], bl);
                    mma_bf16(acc[mf][2 * p],     al[mf], bh);
                    mma_bf16(acc[mf][2 * p + 1], ah[mf], bh + 2);
                    mma_bf16(acc[mf][2 * p + 1], ah[mf], bl + 2);
                    mma_bf16(acc[mf][2 * p + 1], al[mf], bh + 2);
                }
            }
        }

        if (it < 7) {
            STORE_A(buf ^ 1);
            asm volatile("cp.async.wait_group 0;");
        }
        __syncthreads();
    }

    // epilogue: C fragment owner map — c0,c1: (row g, col 2*tig,+1); c2,c3: row g+8
    const int g   = lane >> 2;
    const int tig = lane & 3;

    if (!FUSE) {
#pragma unroll
        for (int mf = 0; mf < 2; mf++)
#pragma unroll
        for (int half = 0; half < 2; half++) {
            int r = m0 + wm * 32 + mf * 16 + g + half * 8;
            if (r >= M) continue;
#pragma unroll
            for (int nf = 0; nf < 8; nf++) {
                int col = wn * 64 + nf * 8 + tig * 2;
                *(float2*)&g_ft[(size_t)r * DIM + col] =
                    make_float2(acc[mf][nf][half * 2], acc[mf][nf][half * 2 + 1]);
            }
        }
    } else {
#pragma unroll
        for (int mf = 0; mf < 2; mf++)
#pragma unroll
        for (int half = 0; half < 2; half++) {
            int e  = m0 + wm * 32 + mf * 16 + g + half * 8;
            int sn = src[e], dn = dst[e];
            float dot = 0.0f;
#pragma unroll
            for (int nf = 0; nf < 8; nf++) {
                int col = wn * 64 + nf * 8 + tig * 2;
                float2 fs = *(const float2*)&g_ft[(size_t)sn * DIM + col];
                float2 fd = *(const float2*)&g_ft[(size_t)dn * DIM + col];
                float px = acc[mf][nf][half * 2]     + fs.x;
                float py = acc[mf][nf][half * 2 + 1] + fs.y;
                *(float2*)&g_ftp[(size_t)e * DIM + col] = make_float2(px, py);
                dot += px * fd.x + py * fd.y;
            }
            dot += __shfl_xor_sync(0xffffffffu, dot, 1);
            dot += __shfl_xor_sync(0xffffffffu, dot, 2);
            if (tig == 0)
                g_a[(size_t)e * NHEAD + wn] = dot;
        }
    }
#undef LOAD_A
#undef STORE_A
#undef CP_B
}

// ---------------- segment max: monotonic-uint encode + native atomicMax -------
__global__ void segmax_kernel(const int* __restrict__ dst) {
    int i = blockIdx.x * blockDim.x + threadIdx.x;   // E*H threads
    if (i >= N_EDGES * NHEAD) return;
    int e = i >> 2, h = i & 3;
    unsigned b = __float_as_uint(g_a[i]);
    unsigned k = (b & 0x80000000u) ? ~b : (b | 0x80000000u);
    atomicMax(&g_me[(size_t)dst[e] * NHEAD + h], k);
}

// ---------------- exp + segment sum -------------------------------------------
__global__ void expsum_kernel(const int* __restrict__ dst) {
    int i = blockIdx.x * blockDim.x + threadIdx.x;   // E*H threads
    if (i >= N_EDGES * NHEAD) return;
    int e = i >> 2, h = i & 3;
    int d = dst[e];
    unsigned k = g_me[(size_t)d * NHEAD + h];
    float m = (k & 0x80000000u) ? __uint_as_float(k ^ 0x80000000u)
                                : __uint_as_float(~k);
    float ex = expf(g_a[i] - m);
    g_a[i] = ex;
    atomicAdd(&g_s[(size_t)d * NHEAD + h], ex);
}

// ---------------- weighted scatter-sum aggregation (2x red.v4 / thread) -------
__global__ void agg_kernel(const int* __restrict__ dst, float* __restrict__ out) {
    int t = blockIdx.x * blockDim.x + threadIdx.x;   // E*32 threads
    if (t >= N_EDGES * 32) return;
    int e  = t >> 5;
    int c  = (t & 31) << 3;     // column 0..248 (8 floats, within one head)
    int h  = c >> 6;            // head
    int d  = dst[e];
    float sa = g_a[(size_t)e * NHEAD + h] / g_s[(size_t)d * NHEAD + h] * 0.125f;
    float4 f0 = *(const float4*)&g_ftp[(size_t)e * DIM + c];
    float4 f1 = *(const float4*)&g_ftp[(size_t)e * DIM + c + 4];
    float* o = &out[(size_t)d * DIM + c];
    asm volatile("red.global.add.v4.f32 [%0], {%1,%2,%3,%4};"
        :: "l"(o), "f"(sa * f0.x), "f"(sa * f0.y), "f"(sa * f0.z), "f"(sa * f0.w)
        : "memory");
    asm volatile("red.global.add.v4.f32 [%0], {%1,%2,%3,%4};"
        :: "l"(o + 4), "f"(sa * f1.x), "f"(sa * f1.y), "f"(sa * f1.z), "f"(sa * f1.w)
        : "memory");
}

// ---------------- launch -------------------------------------------------------
extern "C" void kernel_launch(void* const* d_in, const int* in_sizes, int n_in,
                              void* d_out, int out_size) {
    const float* nfeat  = (const float*)d_in[0];
    const float* efeat  = (const float*)d_in[1];
    const int*   src    = (const int*)  d_in[2];
    const int*   dst    = (const int*)  d_in[3];
    const float* W_node = (const float*)d_in[4];
    const float* W_edge = (const float*)d_in[5];
    float* out = (float*)d_out;

    cudaFuncSetAttribute(gemm_mma_kernel<false>,
        cudaFuncAttributeMaxDynamicSharedMemorySize, SMEM_BYTES);
    cudaFuncSetAttribute(gemm_mma_kernel<true>,
        cudaFuncAttributeMaxDynamicSharedMemorySize, SMEM_BYTES);

    // 1. init: zero output, init segment max/sum, split weights to bf16 hi/lo
    init_kernel<<<(N_NODES * DIM + 255) / 256, 256>>>(out, W_node, W_edge);

    // 2. node projection: g_ft = nfeat @ W_node  (157 blocks, tail-guarded)
    gemm_mma_kernel<false><<<(N_NODES + BM - 1) / BM, 512, SMEM_BYTES>>>(
        nfeat, 0, nullptr, nullptr, N_NODES);

    // 3. fused edge GEMM + gather-add + per-head dot (2500 blocks)
    gemm_mma_kernel<true><<<N_EDGES / BM, 512, SMEM_BYTES>>>(
        efeat, 1, src, dst, N_EDGES);

    // 4. segment max over destination nodes
    segmax_kernel<<<(N_EDGES * NHEAD + 255) / 256, 256>>>(dst);

    // 5. exp + segment sum
    expsum_kernel<<<(N_EDGES * NHEAD + 255) / 256, 256>>>(dst);

    // 6. weighted scatter aggregation
    agg_kernel<<<(N_EDGES * 32 + 255) / 256, 256>>>(dst, out);
}